// round 5
// baseline (speedup 1.0000x reference)
#include <cuda_runtime.h>

// QuantumConvLayer: probs = [c^4, c^2 s^2, s^4, s^2 c^2],
// c^2 = (1+cos x)/2, s^2 = (1-cos x)/2, x = inputs[i,0].
// HBM-bound streaming: 256MB read (every 32B input sector touched) + 256MB write.
// R4: single-wave persistent grid-stride kernel (1184 blocks = 148 SMs x 8),
// RPT=4 front-batched loads, plain ldg/store (R2 sweet spot).

#define RPT 4
#define TPB 256
#define ROWS_PER_TILE (RPT * TPB)   // 1024
#define GRID_BLOCKS (148 * 8)       // one full wave on GB300 (148+ SMs)

__device__ __forceinline__ float4 qprobs(float x)
{
    float cx = __cosf(x);
    float c2 = 0.5f + 0.5f * cx;   // cos^2(x/2)
    float s2 = 0.5f - 0.5f * cx;   // sin^2(x/2)
    float cs = c2 * s2;
    return make_float4(c2 * c2, cs, s2 * s2, cs);
}

__global__ void __launch_bounds__(TPB) qconv_kernel(
    const float* __restrict__ in,   // [N,4] row-major; only col 0 read
    float4* __restrict__ out,       // [N]
    int n)
{
    int t = threadIdx.x;
    int n_tiles = (n + ROWS_PER_TILE - 1) / ROWS_PER_TILE;

    for (int tile_idx = blockIdx.x; tile_idx < n_tiles; tile_idx += gridDim.x) {
        int tile = tile_idx * ROWS_PER_TILE;

        if (tile + ROWS_PER_TILE <= n) {
            // Fast path: no per-row bounds checks; 4 independent front-batched loads.
            float x[RPT];
#pragma unroll
            for (int k = 0; k < RPT; k++)
                x[k] = __ldg(in + 4 * (size_t)(tile + t + TPB * k));
#pragma unroll
            for (int k = 0; k < RPT; k++)
                out[tile + t + TPB * k] = qprobs(x[k]);
        } else {
#pragma unroll
            for (int k = 0; k < RPT; k++) {
                int row = tile + t + TPB * k;
                if (row < n)
                    out[row] = qprobs(__ldg(in + 4 * (size_t)row));
            }
        }
    }
}

extern "C" void kernel_launch(void* const* d_in, const int* in_sizes, int n_in,
                              void* d_out, int out_size)
{
    const float* in = (const float*)d_in[0];
    float4* out = (float4*)d_out;
    int n = in_sizes[0] / 4;   // rows

    int n_tiles = (n + ROWS_PER_TILE - 1) / ROWS_PER_TILE;
    int grid = n_tiles < GRID_BLOCKS ? n_tiles : GRID_BLOCKS;
    qconv_kernel<<<grid, TPB>>>(in, out, n);
}

// round 6
// speedup vs baseline: 1.1249x; 1.1249x over previous
#include <cuda_runtime.h>

// QuantumConvLayer: probs = [c^4, c^2 s^2, s^4, s^2 c^2],
// c^2 = (1+cos x)/2, s^2 = (1-cos x)/2, x = inputs[i,0].
// HBM-bound streaming: 256MB read + 256MB write (both mandatory).
// R5: R2 structure (flat grid, TPB=256, RPT=4, front-batched loads) but the
// input row is loaded as a dense float4 (LDG.128): warp loads become fully
// contiguous 512B blocks -> full-line L2 read requests, fewer L1tex wavefronts.

#define RPT 4
#define TPB 256
#define ROWS_PER_BLOCK (RPT * TPB)   // 1024

__device__ __forceinline__ float4 qprobs(float x)
{
    float cx = __cosf(x);
    float c2 = 0.5f + 0.5f * cx;   // cos^2(x/2)
    float s2 = 0.5f - 0.5f * cx;   // sin^2(x/2)
    float cs = c2 * s2;
    return make_float4(c2 * c2, cs, s2 * s2, cs);
}

__global__ void __launch_bounds__(TPB) qconv_kernel(
    const float4* __restrict__ in,  // [N] rows, 16B each; only .x (col 0) used
    float4* __restrict__ out,       // [N]
    int n)
{
    int tile = blockIdx.x * ROWS_PER_BLOCK;
    int t = threadIdx.x;

    float x[RPT];
    int row[RPT];

    // Front-batch 4 independent dense LDG.128s (warp = 512B contiguous each)
#pragma unroll
    for (int k = 0; k < RPT; k++) {
        row[k] = tile + t + TPB * k;
        x[k] = (row[k] < n) ? __ldg(in + row[k]).x : 0.0f;
    }

#pragma unroll
    for (int k = 0; k < RPT; k++) {
        if (row[k] < n)
            out[row[k]] = qprobs(x[k]);
    }
}

extern "C" void kernel_launch(void* const* d_in, const int* in_sizes, int n_in,
                              void* d_out, int out_size)
{
    const float4* in = (const float4*)d_in[0];
    float4* out = (float4*)d_out;
    int n = in_sizes[0] / 4;   // rows

    int grid = (n + ROWS_PER_BLOCK - 1) / ROWS_PER_BLOCK;
    qconv_kernel<<<grid, TPB>>>(in, out, n);
}